// round 3
// baseline (speedup 1.0000x reference)
#include <cuda_runtime.h>
#include <cuda_fp16.h>
#include <cstdint>

#define BATCH 256
#define N_GENES 8192
#define WM 4
#define HID (N_GENES * WM)       // 32768
#define N_TF 1024
#define GPT 64
#define EDGES3 (GPT * WM)        // 256
#define EPS 1e-5f
#define GENES_PER_BLOCK 16

// Scratch: layer-2 output stored TRANSPOSED in fp16: hT[col * BATCH + b]
__device__ __half g_hT[HID * BATCH];

__device__ __forceinline__ float warp_sum(float v) {
#pragma unroll
    for (int o = 16; o; o >>= 1) v += __shfl_xor_sync(0xffffffffu, v, o);
    return v;
}

// Fused: layer1 (fan_in 1) -> relu -> BN -> layer2 (4x4 per-gene) -> relu -> BN
// One warp per gene (4 columns x 256 batch rows; 8 rows per lane). 16 genes/block.
__global__ __launch_bounds__(512) void k_layers12(
    const float* __restrict__ x,    // [BATCH, N_GENES] row-major
    const float* __restrict__ w1, const float* __restrict__ b1,
    const float* __restrict__ w2, const float* __restrict__ b2)
{
    __shared__ float sx[BATCH][GENES_PER_BLOCK + 1];

    const int g0 = blockIdx.x * GENES_PER_BLOCK;
    const int t = threadIdx.x;
    const int warp = t >> 5;
    const int lane = t & 31;

    // Load tile x[0:256, g0:g0+16]  (4096 elems, 8 per thread)
#pragma unroll
    for (int i = 0; i < 8; i++) {
        int elem = i * 512 + t;
        int r = elem >> 4;
        int c = elem & 15;
        sx[r][c] = x[r * N_GENES + g0 + c];
    }
    __syncthreads();

    const int gi = warp;           // one gene per warp
    const int g = g0 + gi;

    float w1v[4], b1v[4], b2v[4], w2v[16];
#pragma unroll
    for (int j = 0; j < 4; j++) {
        w1v[j] = w1[4 * g + j];
        b1v[j] = b1[4 * g + j];
        b2v[j] = b2[4 * g + j];
    }
#pragma unroll
    for (int e = 0; e < 16; e++) w2v[e] = w2[16 * g + e];

    // layer1 + relu ; lane handles batches b = lane + 32k
    float h1[8][4];
#pragma unroll
    for (int k = 0; k < 8; k++) {
        float xv = sx[lane + 32 * k][gi];
#pragma unroll
        for (int j = 0; j < 4; j++)
            h1[k][j] = fmaxf(fmaf(w1v[j], xv, b1v[j]), 0.0f);
    }

    // BatchNorm per column j (two-pass, warp-local)
#pragma unroll
    for (int j = 0; j < 4; j++) {
        float s = 0.f;
#pragma unroll
        for (int k = 0; k < 8; k++) s += h1[k][j];
        float m = warp_sum(s) * (1.0f / BATCH);
        float vs = 0.f;
#pragma unroll
        for (int k = 0; k < 8; k++) { float d = h1[k][j] - m; vs += d * d; }
        float inv = rsqrtf(warp_sum(vs) * (1.0f / BATCH) + EPS);
#pragma unroll
        for (int k = 0; k < 8; k++) h1[k][j] = (h1[k][j] - m) * inv;
    }

    // layer2 (4x4 dense per gene) + relu
    float h2[8][4];
#pragma unroll
    for (int k = 0; k < 8; k++) {
#pragma unroll
        for (int i = 0; i < 4; i++) {
            float acc = b2v[i];
#pragma unroll
            for (int j = 0; j < 4; j++) acc = fmaf(w2v[4 * i + j], h1[k][j], acc);
            h2[k][i] = fmaxf(acc, 0.0f);
        }
    }

    // BatchNorm per column i, then transposed fp16 store
#pragma unroll
    for (int i = 0; i < 4; i++) {
        float s = 0.f;
#pragma unroll
        for (int k = 0; k < 8; k++) s += h2[k][i];
        float m = warp_sum(s) * (1.0f / BATCH);
        float vs = 0.f;
#pragma unroll
        for (int k = 0; k < 8; k++) { float d = h2[k][i] - m; vs += d * d; }
        float inv = rsqrtf(warp_sum(vs) * (1.0f / BATCH) + EPS);
        __half* dst = &g_hT[(4 * g + i) * BATCH];
#pragma unroll
        for (int k = 0; k < 8; k++)
            dst[lane + 32 * k] = __float2half_rn((h2[k][i] - m) * inv);
    }
}

// layer3 gather + final BN. One block (256 threads) per TF; thread = batch elem.
// (w, col*BATCH) packed as 8 bytes in shared -> single LDS.64 per edge.
struct __align__(8) WC { float w; int off; };

__global__ __launch_bounds__(256, 8) void k_layer3(
    const float* __restrict__ w3, const float* __restrict__ b3,
    const int* __restrict__ cols3,
    float* __restrict__ out)   // [BATCH, N_TF]
{
    const int tf = blockIdx.x;
    const int b = threadIdx.x;        // batch index 0..255
    const int warp = b >> 5;
    const int lane = b & 31;

    __shared__ WC swc[EDGES3];
    __shared__ float sred[8];

    swc[b].w   = w3[tf * EDGES3 + b];
    swc[b].off = cols3[tf * EDGES3 + b] * BATCH;
    __syncthreads();

    // Two independent edge streams for MLP + split FFMA dependency chain.
    float acc0 = b3[tf];
    float acc1 = 0.0f;
#pragma unroll 4
    for (int e = 0; e < EDGES3 / 2; e++) {
        WC a = swc[e];
        WC c = swc[e + EDGES3 / 2];
        acc0 = fmaf(a.w, __half2float(g_hT[a.off + b]), acc0);
        acc1 = fmaf(c.w, __half2float(g_hT[c.off + b]), acc1);
    }
    float acc = acc0 + acc1;

    // BN over 256 batch values (two-pass, block reduction over 8 warps)
    float s = warp_sum(acc);
    if (lane == 0) sred[warp] = s;
    __syncthreads();
    float m = 0.f;
#pragma unroll
    for (int i = 0; i < 8; i++) m += sred[i];
    m *= (1.0f / BATCH);
    __syncthreads();

    float d = acc - m;
    float v = warp_sum(d * d);
    if (lane == 0) sred[warp] = v;
    __syncthreads();
    float var = 0.f;
#pragma unroll
    for (int i = 0; i < 8; i++) var += sred[i];
    var *= (1.0f / BATCH);

    out[b * N_TF + tf] = d * rsqrtf(var + EPS);
}

extern "C" void kernel_launch(void* const* d_in, const int* in_sizes, int n_in,
                              void* d_out, int out_size)
{
    const float* x  = (const float*)d_in[0];
    const float* w1 = (const float*)d_in[1];
    const float* b1 = (const float*)d_in[2];
    const float* w2 = (const float*)d_in[3];
    const float* b2 = (const float*)d_in[4];
    const float* w3 = (const float*)d_in[5];
    const float* b3 = (const float*)d_in[6];
    const int* cols3 = (const int*)d_in[12];
    float* out = (float*)d_out;

    k_layers12<<<N_GENES / GENES_PER_BLOCK, 512>>>(x, w1, b1, w2, b2);
    k_layer3<<<N_TF, 256>>>(w3, b3, cols3, out);
}

// round 4
// speedup vs baseline: 1.1632x; 1.1632x over previous
#include <cuda_runtime.h>
#include <cuda_fp16.h>
#include <cstdint>

#define BATCH 256
#define N_GENES 8192
#define WM 4
#define HID (N_GENES * WM)       // 32768
#define N_TF 1024
#define GPT 64
#define EDGES3 (GPT * WM)        // 256
#define EPS 1e-5f
#define GENES_PER_BLOCK 16

// Scratch: layer-2 output stored TRANSPOSED in fp16: hT[col * BATCH + b]
__device__ __half g_hT[HID * BATCH];

__device__ __forceinline__ float warp_sum(float v) {
#pragma unroll
    for (int o = 16; o; o >>= 1) v += __shfl_xor_sync(0xffffffffu, v, o);
    return v;
}

// Fused: layer1 (fan_in 1) -> relu -> BN -> layer2 (4x4 per-gene) -> relu -> BN
// One warp per gene. Lane owns batch pairs b = 2*lane + 64*k (+0/+1), k=0..3,
// so the transposed hT store is a coalesced __half2 store.
__global__ __launch_bounds__(512) void k_layers12(
    const float* __restrict__ x,    // [BATCH, N_GENES] row-major
    const float* __restrict__ w1, const float* __restrict__ b1,
    const float* __restrict__ w2, const float* __restrict__ b2)
{
    __shared__ float sx[BATCH][GENES_PER_BLOCK + 1];

    const int g0 = blockIdx.x * GENES_PER_BLOCK;
    const int t = threadIdx.x;
    const int warp = t >> 5;
    const int lane = t & 31;

    // Load tile x[0:256, g0:g0+16]  (4096 elems, 8 per thread)
#pragma unroll
    for (int i = 0; i < 8; i++) {
        int elem = i * 512 + t;
        int r = elem >> 4;
        int c = elem & 15;
        sx[r][c] = x[r * N_GENES + g0 + c];
    }
    __syncthreads();

    const int gi = warp;           // one gene per warp
    const int g = g0 + gi;

    float w1v[4], b1v[4], b2v[4], w2v[16];
#pragma unroll
    for (int j = 0; j < 4; j++) {
        w1v[j] = w1[4 * g + j];
        b1v[j] = b1[4 * g + j];
        b2v[j] = b2[4 * g + j];
    }
#pragma unroll
    for (int e = 0; e < 16; e++) w2v[e] = w2[16 * g + e];

    // layer1 + relu ; lane handles batches 2*lane+64*k and 2*lane+1+64*k
    float h1[4][2][4];
#pragma unroll
    for (int k = 0; k < 4; k++) {
#pragma unroll
        for (int p = 0; p < 2; p++) {
            float xv = sx[2 * lane + p + 64 * k][gi];
#pragma unroll
            for (int j = 0; j < 4; j++)
                h1[k][p][j] = fmaxf(fmaf(w1v[j], xv, b1v[j]), 0.0f);
        }
    }

    // BatchNorm per column j (two-pass, warp-local)
#pragma unroll
    for (int j = 0; j < 4; j++) {
        float s = 0.f;
#pragma unroll
        for (int k = 0; k < 4; k++) s += h1[k][0][j] + h1[k][1][j];
        float m = warp_sum(s) * (1.0f / BATCH);
        float vs = 0.f;
#pragma unroll
        for (int k = 0; k < 4; k++) {
#pragma unroll
            for (int p = 0; p < 2; p++) { float d = h1[k][p][j] - m; vs += d * d; }
        }
        float inv = rsqrtf(warp_sum(vs) * (1.0f / BATCH) + EPS);
#pragma unroll
        for (int k = 0; k < 4; k++) {
            h1[k][0][j] = (h1[k][0][j] - m) * inv;
            h1[k][1][j] = (h1[k][1][j] - m) * inv;
        }
    }

    // layer2 (4x4 dense per gene) + relu
    float h2[4][2][4];
#pragma unroll
    for (int k = 0; k < 4; k++) {
#pragma unroll
        for (int p = 0; p < 2; p++) {
#pragma unroll
            for (int i = 0; i < 4; i++) {
                float acc = b2v[i];
#pragma unroll
                for (int j = 0; j < 4; j++) acc = fmaf(w2v[4 * i + j], h1[k][p][j], acc);
                h2[k][p][i] = fmaxf(acc, 0.0f);
            }
        }
    }

    // BatchNorm per column i, then transposed coalesced half2 store
#pragma unroll
    for (int i = 0; i < 4; i++) {
        float s = 0.f;
#pragma unroll
        for (int k = 0; k < 4; k++) s += h2[k][0][i] + h2[k][1][i];
        float m = warp_sum(s) * (1.0f / BATCH);
        float vs = 0.f;
#pragma unroll
        for (int k = 0; k < 4; k++) {
#pragma unroll
            for (int p = 0; p < 2; p++) { float d = h2[k][p][i] - m; vs += d * d; }
        }
        float inv = rsqrtf(warp_sum(vs) * (1.0f / BATCH) + EPS);
        __half2* dst = reinterpret_cast<__half2*>(&g_hT[(4 * g + i) * BATCH]);
#pragma unroll
        for (int k = 0; k < 4; k++) {
            float2 f = make_float2((h2[k][0][i] - m) * inv, (h2[k][1][i] - m) * inv);
            dst[lane + 32 * k] = __float22half2_rn(f);
        }
    }
}

// layer3 gather + final BN. One block (256 threads) per TF.
// Edge dimension split across thread-halves: threads 0-127 do edges 0-127,
// threads 128-255 do edges 128-255, each on batch pair (2*bt, 2*bt+1) via
// __half2 loads. Partials combined through shared memory.
struct __align__(8) WC { float w; int off; };

__global__ __launch_bounds__(256, 8) void k_layer3(
    const float* __restrict__ w3, const float* __restrict__ b3,
    const int* __restrict__ cols3,
    float* __restrict__ out)   // [BATCH, N_TF]
{
    const int tf = blockIdx.x;
    const int t = threadIdx.x;        // 0..255
    const int half = t >> 7;          // which 128-edge half
    const int bt = t & 127;           // batch-pair index
    const int warp = t >> 5;
    const int lane = t & 31;

    __shared__ WC swc[EDGES3];
    __shared__ float2 spart[128];
    __shared__ float sred[4];

    swc[t].w   = w3[tf * EDGES3 + t];
    swc[t].off = cols3[tf * EDGES3 + t] * BATCH;
    __syncthreads();

    const WC* base = swc + half * (EDGES3 / 2);
    float2 acc = make_float2(0.f, 0.f);
#pragma unroll 8
    for (int e = 0; e < EDGES3 / 2; e++) {
        WC a = base[e];
        __half2 hv = *reinterpret_cast<const __half2*>(&g_hT[a.off + 2 * bt]);
        float2 f = __half22float2(hv);
        acc.x = fmaf(a.w, f.x, acc.x);
        acc.y = fmaf(a.w, f.y, acc.y);
    }

    if (half == 1) spart[bt] = acc;
    __syncthreads();

    float bias = b3[tf];
    float2 tot;
    tot.x = acc.x + spart[bt].x + bias;   // garbage for half==1 threads (unused)
    tot.y = acc.y + spart[bt].y + bias;

    // BN over 256 batch values; warps 0-3 (half==0) hold all of them.
    float s = warp_sum(tot.x + tot.y);
    if (lane == 0 && warp < 4) sred[warp] = s;
    __syncthreads();
    float m = (sred[0] + sred[1] + sred[2] + sred[3]) * (1.0f / BATCH);
    __syncthreads();

    float dx = tot.x - m, dy = tot.y - m;
    float v = warp_sum(dx * dx + dy * dy);
    if (lane == 0 && warp < 4) sred[warp] = v;
    __syncthreads();
    float var = (sred[0] + sred[1] + sred[2] + sred[3]) * (1.0f / BATCH);
    float inv = rsqrtf(var + EPS);

    if (half == 0) {
        out[(2 * bt)     * N_TF + tf] = dx * inv;
        out[(2 * bt + 1) * N_TF + tf] = dy * inv;
    }
}

extern "C" void kernel_launch(void* const* d_in, const int* in_sizes, int n_in,
                              void* d_out, int out_size)
{
    const float* x  = (const float*)d_in[0];
    const float* w1 = (const float*)d_in[1];
    const float* b1 = (const float*)d_in[2];
    const float* w2 = (const float*)d_in[3];
    const float* b2 = (const float*)d_in[4];
    const float* w3 = (const float*)d_in[5];
    const float* b3 = (const float*)d_in[6];
    const int* cols3 = (const int*)d_in[12];
    float* out = (float*)d_out;

    k_layers12<<<N_GENES / GENES_PER_BLOCK, 512>>>(x, w1, b1, w2, b2);
    k_layer3<<<N_TF, 256>>>(w3, b3, cols3, out);
}

// round 5
// speedup vs baseline: 1.4848x; 1.2765x over previous
#include <cuda_runtime.h>
#include <cuda_fp16.h>
#include <cstdint>

#define BATCH 256
#define N_GENES 8192
#define WM 4
#define HID (N_GENES * WM)       // 32768
#define N_TF 1024
#define GPT 64
#define EDGES3 (GPT * WM)        // 256
#define EPS 1e-5f
#define GENES_PER_BLOCK 8

// Scratch: layer-2 output stored TRANSPOSED in fp16: hT[col * BATCH + b]
__device__ __half g_hT[HID * BATCH];

__device__ __forceinline__ float2 warp_sum2(float2 v) {
#pragma unroll
    for (int o = 16; o; o >>= 1) {
        v.x += __shfl_xor_sync(0xffffffffu, v.x, o);
        v.y += __shfl_xor_sync(0xffffffffu, v.y, o);
    }
    return v;
}

// Fused: layer1 (fan_in 1) -> relu -> BN -> layer2 (4x4 per-gene) -> relu -> BN
// One warp per gene. Lane owns batch pairs b = 2*lane + 64*k (+0/+1), k=0..3.
// x tile is kept TRANSPOSED in smem (sxT[gene][batch], padded) so the paired
// read is one conflict-free LDS.64.
__global__ __launch_bounds__(256) void k_layers12(
    const float* __restrict__ x,    // [BATCH, N_GENES] row-major
    const float* __restrict__ w1, const float* __restrict__ b1,
    const float* __restrict__ w2, const float* __restrict__ b2)
{
    __shared__ float sxT[GENES_PER_BLOCK][BATCH + 2];

    const int g0 = blockIdx.x * GENES_PER_BLOCK;
    const int t = threadIdx.x;
    const int warp = t >> 5;
    const int lane = t & 31;

    // Load tile x[0:256, g0:g0+8] transposed into smem.
#pragma unroll
    for (int i = 0; i < 8; i++) {
        int elem = i * 256 + t;
        int b = elem >> 3;
        int c = elem & 7;
        sxT[c][b] = x[b * N_GENES + g0 + c];
    }
    __syncthreads();

    const int gi = warp;           // one gene per warp
    const int g = g0 + gi;

    float w1v[4], b1v[4], b2v[4], w2v[16];
#pragma unroll
    for (int j = 0; j < 4; j++) {
        w1v[j] = w1[4 * g + j];
        b1v[j] = b1[4 * g + j];
        b2v[j] = b2[4 * g + j];
    }
#pragma unroll
    for (int e = 0; e < 16; e++) w2v[e] = w2[16 * g + e];

    // layer1 + relu ; lane handles batches 2*lane+64*k (+0/+1)
    float h1[4][2][4];
#pragma unroll
    for (int k = 0; k < 4; k++) {
        float2 xv = *reinterpret_cast<const float2*>(&sxT[gi][2 * lane + 64 * k]);
#pragma unroll
        for (int j = 0; j < 4; j++) {
            h1[k][0][j] = fmaxf(fmaf(w1v[j], xv.x, b1v[j]), 0.0f);
            h1[k][1][j] = fmaxf(fmaf(w1v[j], xv.y, b1v[j]), 0.0f);
        }
    }

    // BatchNorm per column j — single pass (sum, sumsq) warp reduction
#pragma unroll
    for (int j = 0; j < 4; j++) {
        float2 ss = make_float2(0.f, 0.f);
#pragma unroll
        for (int k = 0; k < 4; k++) {
#pragma unroll
            for (int p = 0; p < 2; p++) {
                float h = h1[k][p][j];
                ss.x += h; ss.y += h * h;
            }
        }
        ss = warp_sum2(ss);
        float m = ss.x * (1.0f / BATCH);
        float var = fmaxf(ss.y * (1.0f / BATCH) - m * m, 0.0f);
        float inv = rsqrtf(var + EPS);
#pragma unroll
        for (int k = 0; k < 4; k++) {
            h1[k][0][j] = (h1[k][0][j] - m) * inv;
            h1[k][1][j] = (h1[k][1][j] - m) * inv;
        }
    }

    // layer2 (4x4 dense per gene) + relu
    float h2[4][2][4];
#pragma unroll
    for (int k = 0; k < 4; k++) {
#pragma unroll
        for (int p = 0; p < 2; p++) {
#pragma unroll
            for (int i = 0; i < 4; i++) {
                float acc = b2v[i];
#pragma unroll
                for (int j = 0; j < 4; j++) acc = fmaf(w2v[4 * i + j], h1[k][p][j], acc);
                h2[k][p][i] = fmaxf(acc, 0.0f);
            }
        }
    }

    // BatchNorm per column i (single pass), then transposed coalesced half2 store
#pragma unroll
    for (int i = 0; i < 4; i++) {
        float2 ss = make_float2(0.f, 0.f);
#pragma unroll
        for (int k = 0; k < 4; k++) {
#pragma unroll
            for (int p = 0; p < 2; p++) {
                float h = h2[k][p][i];
                ss.x += h; ss.y += h * h;
            }
        }
        ss = warp_sum2(ss);
        float m = ss.x * (1.0f / BATCH);
        float var = fmaxf(ss.y * (1.0f / BATCH) - m * m, 0.0f);
        float inv = rsqrtf(var + EPS);
        __half2* dst = reinterpret_cast<__half2*>(&g_hT[(4 * g + i) * BATCH]);
#pragma unroll
        for (int k = 0; k < 4; k++) {
            float2 f = make_float2((h2[k][0][i] - m) * inv, (h2[k][1][i] - m) * inv);
            dst[lane + 32 * k] = __float22half2_rn(f);
        }
    }
}

// layer3: one block (8 warps) per TF. Each warp processes 32 edges; one
// LDG.128 per lane per edge covers the whole 512 B column (8 batches/lane,
// 8 independent accumulators). Cross-warp combine in smem, single-pass BN.
struct __align__(8) WC { float w; int boff; };   // boff = byte offset of column

__global__ __launch_bounds__(256, 8) void k_layer3(
    const float* __restrict__ w3, const float* __restrict__ b3,
    const int* __restrict__ cols3,
    float* __restrict__ out)   // [BATCH, N_TF]
{
    const int tf = blockIdx.x;
    const int t = threadIdx.x;        // 0..255
    const int warp = t >> 5;
    const int lane = t & 31;

    __shared__ WC swc[EDGES3];
    __shared__ float sacc[8][BATCH];      // 8 KB
    __shared__ float2 sred[8];

    swc[t].w    = w3[tf * EDGES3 + t];
    swc[t].boff = cols3[tf * EDGES3 + t] * (BATCH * 2);   // bytes
    __syncthreads();

    const char* hbase = reinterpret_cast<const char*>(g_hT) + lane * 16;

    float acc[8];
#pragma unroll
    for (int s = 0; s < 8; s++) acc[s] = 0.f;

#pragma unroll 8
    for (int j = 0; j < 32; j++) {
        WC a = swc[warp * 32 + j];
        uint4 v = *reinterpret_cast<const uint4*>(hbase + a.boff);
        float2 f0 = __half22float2(*reinterpret_cast<__half2*>(&v.x));
        float2 f1 = __half22float2(*reinterpret_cast<__half2*>(&v.y));
        float2 f2 = __half22float2(*reinterpret_cast<__half2*>(&v.z));
        float2 f3 = __half22float2(*reinterpret_cast<__half2*>(&v.w));
        acc[0] = fmaf(a.w, f0.x, acc[0]);
        acc[1] = fmaf(a.w, f0.y, acc[1]);
        acc[2] = fmaf(a.w, f1.x, acc[2]);
        acc[3] = fmaf(a.w, f1.y, acc[3]);
        acc[4] = fmaf(a.w, f2.x, acc[4]);
        acc[5] = fmaf(a.w, f2.y, acc[5]);
        acc[6] = fmaf(a.w, f3.x, acc[6]);
        acc[7] = fmaf(a.w, f3.y, acc[7]);
    }

    // Park partials: warp's acc[s] is batch 8*lane+s
    *reinterpret_cast<float4*>(&sacc[warp][8 * lane])     = make_float4(acc[0], acc[1], acc[2], acc[3]);
    *reinterpret_cast<float4*>(&sacc[warp][8 * lane + 4]) = make_float4(acc[4], acc[5], acc[6], acc[7]);
    __syncthreads();

    // Thread t owns batch b = t: sum over the 8 warps' partials.
    float z = b3[tf];
#pragma unroll
    for (int w = 0; w < 8; w++) z += sacc[w][t];

    // Single-pass BN over the 256 batch values.
    float2 ss = warp_sum2(make_float2(z, z * z));
    if (lane == 0) sred[warp] = ss;
    __syncthreads();
    float S = 0.f, S2 = 0.f;
#pragma unroll
    for (int i = 0; i < 8; i++) { S += sred[i].x; S2 += sred[i].y; }
    float m = S * (1.0f / BATCH);
    float var = fmaxf(S2 * (1.0f / BATCH) - m * m, 0.0f);
    float inv = rsqrtf(var + EPS);

    out[t * N_TF + tf] = (z - m) * inv;
}

extern "C" void kernel_launch(void* const* d_in, const int* in_sizes, int n_in,
                              void* d_out, int out_size)
{
    const float* x  = (const float*)d_in[0];
    const float* w1 = (const float*)d_in[1];
    const float* b1 = (const float*)d_in[2];
    const float* w2 = (const float*)d_in[3];
    const float* b2 = (const float*)d_in[4];
    const float* w3 = (const float*)d_in[5];
    const float* b3 = (const float*)d_in[6];
    const int* cols3 = (const int*)d_in[12];
    float* out = (float*)d_out;

    k_layers12<<<N_GENES / GENES_PER_BLOCK, 256>>>(x, w1, b1, w2, b2);
    k_layer3<<<N_TF, 256>>>(w3, b3, cols3, out);
}